// round 6
// baseline (speedup 1.0000x reference)
#include <cuda_runtime.h>
#include <cstdint>

// Problem constants
#define VSZ   32000
#define HSZ   512
#define BSZ   16
#define TSZ   128
#define G4    2048           // 4*H
#define NROW  2048           // T*B rows
#define OUT_HF 65536000      // B*T*V
#define OUT_CF 65544192      // + B*H

// ---------------- device scratch (no allocations allowed) ----------------
__device__ int      d_toks[NROW];              // token per row r = t*B + b
__device__ float    d_X [(size_t)NROW * HSZ];  // relu(emb[tok])       4 MB
__device__ float    d_Xg[(size_t)NROW * G4];   // X @ W_ih^T + b      16 MB
__device__ float    d_H2[(size_t)NROW * HSZ];  // all h2 states        4 MB
__device__ float    d_hbuf[2 * BSZ * HSZ];     // double-buffered h
__device__ unsigned d_bar;                     // spin barrier counter

// ---------------- helpers ----------------
__device__ __forceinline__ float tf32r(float x) {
    uint32_t u;
    asm("cvt.rna.tf32.f32 %0, %1;" : "=r"(u) : "f"(x));
    return __uint_as_float(u);
}
__device__ __forceinline__ uint32_t fbits(float x) { return __float_as_uint(x); }

__device__ __forceinline__ void mma8(float* d, const uint32_t* a, const uint32_t* b) {
    asm volatile(
        "mma.sync.aligned.m16n8k8.row.col.f32.tf32.tf32.f32 "
        "{%0,%1,%2,%3}, {%4,%5,%6,%7}, {%8,%9}, {%0,%1,%2,%3};"
        : "+f"(d[0]), "+f"(d[1]), "+f"(d[2]), "+f"(d[3])
        : "r"(a[0]), "r"(a[1]), "r"(a[2]), "r"(a[3]), "r"(b[0]), "r"(b[1]));
}

__device__ __forceinline__ float sigf(float x) { return 1.0f / (1.0f + __expf(-x)); }

// ---------------- kernel 0: token prep (+ dtype detect, + barrier reset) ----
__global__ void k_prep(const void* tgt) {
    __shared__ int nz;
    if (threadIdx.x == 0) nz = 0;
    __syncthreads();
    // If target is int64, every hi 32-bit word of the first 1024 tokens is 0
    // (tokens in [0, 32000)). If int32, the odd words are random tokens.
    const unsigned* w = (const unsigned*)tgt;
    for (int i = threadIdx.x; i < 1024; i += blockDim.x)
        if (w[2 * i + 1] != 0u) atomicOr(&nz, 1);
    __syncthreads();
    bool is64 = (nz == 0);
    const long long* p64 = (const long long*)tgt;
    const int*       p32 = (const int*)tgt;
    for (int idx = threadIdx.x; idx < NROW; idx += blockDim.x) {
        int t = idx >> 4, b = idx & 15;          // row r = t*B + b
        int tok;
        if (t == 0) tok = 1;                      // BOS
        else {
            int s = b * TSZ + (t - 1);
            tok = is64 ? (int)p64[s] : p32[s];
        }
        d_toks[idx] = tok;
    }
    if (threadIdx.x == 0) d_bar = 0u;
}

// ---------------- kernel 1: embedding gather + ReLU ----------------
__global__ void k_gather(const float* __restrict__ emb) {
    int r = blockIdx.x;
    int tok = d_toks[r];
    const float4* src = (const float4*)(emb + (size_t)tok * HSZ);
    float4*       dst = (float4*)(d_X + (size_t)r * HSZ);
    float4 v = src[threadIdx.x];                 // 128 threads x float4 = 512
    v.x = fmaxf(v.x, 0.f); v.y = fmaxf(v.y, 0.f);
    v.z = fmaxf(v.z, 0.f); v.w = fmaxf(v.w, 0.f);
    dst[threadIdx.x] = v;
}

// ---------------- GEMM: C[2048, N] = A[2048,512] @ Bmat[N,512]^T + bias ----
// mode 0: A = d_X,  C = d_Xg (N=2048), bias = b_ih + b_hh, rows direct
// mode 1: A = d_H2, C = out  (N=32000), bias = b_out, row r=t*B+b -> b*T+t
__global__ __launch_bounds__(256)
void k_gemm(const float* __restrict__ Bmat, const float* __restrict__ bias1,
            const float* __restrict__ bias2, float* __restrict__ Cout, int mode) {
    __shared__ float As[128][20];
    __shared__ float Bs[128][20];

    const float* A = mode ? d_H2 : d_X;
    float*       C = mode ? Cout : d_Xg;
    const int    N = mode ? VSZ : G4;

    int tM = blockIdx.y, tN = blockIdx.x;
    int tid = threadIdx.x;
    int wid = tid >> 5, lane = tid & 31;
    int gid = lane >> 2, tig = lane & 3;
    int wm = wid >> 2, wn = wid & 3;             // 2 x 4 warps -> 64 x 32 tiles

    float acc[4][4][4];
#pragma unroll
    for (int i = 0; i < 4; i++)
#pragma unroll
        for (int j = 0; j < 4; j++)
#pragma unroll
            for (int k = 0; k < 4; k++) acc[i][j][k] = 0.f;

    int rowL = tid >> 1;                         // 0..127
    int kseg = (tid & 1) * 8;
    const float* Ap = A    + (size_t)(tM * 128 + rowL) * HSZ + kseg;
    const float* Bp = Bmat + (size_t)(tN * 128 + rowL) * HSZ + kseg;

    float4 pa0 = *(const float4*)(Ap);
    float4 pa1 = *(const float4*)(Ap + 4);
    float4 pb0 = *(const float4*)(Bp);
    float4 pb1 = *(const float4*)(Bp + 4);

    for (int kk = 0; kk < HSZ; kk += 16) {
        __syncthreads();
        float4 ca0 = make_float4(tf32r(pa0.x), tf32r(pa0.y), tf32r(pa0.z), tf32r(pa0.w));
        float4 ca1 = make_float4(tf32r(pa1.x), tf32r(pa1.y), tf32r(pa1.z), tf32r(pa1.w));
        float4 cb0 = make_float4(tf32r(pb0.x), tf32r(pb0.y), tf32r(pb0.z), tf32r(pb0.w));
        float4 cb1 = make_float4(tf32r(pb1.x), tf32r(pb1.y), tf32r(pb1.z), tf32r(pb1.w));
        *(float4*)&As[rowL][kseg]     = ca0;
        *(float4*)&As[rowL][kseg + 4] = ca1;
        *(float4*)&Bs[rowL][kseg]     = cb0;
        *(float4*)&Bs[rowL][kseg + 4] = cb1;
        __syncthreads();
        if (kk + 16 < HSZ) {
            pa0 = *(const float4*)(Ap + kk + 16);
            pa1 = *(const float4*)(Ap + kk + 20);
            pb0 = *(const float4*)(Bp + kk + 16);
            pb1 = *(const float4*)(Bp + kk + 20);
        }
#pragma unroll
        for (int k8 = 0; k8 < 16; k8 += 8) {
            uint32_t af[4][4], bf[4][2];
#pragma unroll
            for (int mf = 0; mf < 4; mf++) {
                int m = wm * 64 + mf * 16;
                af[mf][0] = fbits(As[m + gid]    [k8 + tig]);
                af[mf][1] = fbits(As[m + gid + 8][k8 + tig]);
                af[mf][2] = fbits(As[m + gid]    [k8 + tig + 4]);
                af[mf][3] = fbits(As[m + gid + 8][k8 + tig + 4]);
            }
#pragma unroll
            for (int nf = 0; nf < 4; nf++) {
                int n = wn * 32 + nf * 8;
                bf[nf][0] = fbits(Bs[n + gid][k8 + tig]);
                bf[nf][1] = fbits(Bs[n + gid][k8 + tig + 4]);
            }
#pragma unroll
            for (int mf = 0; mf < 4; mf++)
#pragma unroll
                for (int nf = 0; nf < 4; nf++) mma8(acc[mf][nf], af[mf], bf[nf]);
        }
    }

    // epilogue
#pragma unroll
    for (int mf = 0; mf < 4; mf++) {
        int r0 = tM * 128 + wm * 64 + mf * 16 + gid;
        int r1 = r0 + 8;
        int o0 = mode ? ((r0 & 15) * TSZ + (r0 >> 4)) : r0;
        int o1 = mode ? ((r1 & 15) * TSZ + (r1 >> 4)) : r1;
#pragma unroll
        for (int nf = 0; nf < 4; nf++) {
            int cn = tN * 128 + wn * 32 + nf * 8 + tig * 2;
            float bv0, bv1;
            if (mode) { bv0 = bias1[cn]; bv1 = bias1[cn + 1]; }
            else      { bv0 = bias1[cn] + bias2[cn]; bv1 = bias1[cn + 1] + bias2[cn + 1]; }
            float2 v0 = make_float2(acc[mf][nf][0] + bv0, acc[mf][nf][1] + bv1);
            float2 v1 = make_float2(acc[mf][nf][2] + bv0, acc[mf][nf][3] + bv1);
            *(float2*)(C + (size_t)o0 * N + cn) = v0;
            *(float2*)(C + (size_t)o1 * N + cn) = v1;
        }
    }
}

// ---------------- recurrent persistent kernel (32 CTAs) ----------------
// CTA c owns hidden dims [c*16, c*16+16). Local gate rows lr = q*16 + j
// map to global rows q*512 + c*16 + j. Per step: g = Xg[t] + h @ W_hh^T,
// LSTM pointwise, write h2 to double-buffered hbuf + H2, spin barrier.
#define WS_STRIDE 516
#define HS_STRIDE 524
#define RNN_SMEM ((64 * WS_STRIDE + 16 * HS_STRIDE + 8 * 64 * 16) * 4)

__global__ __launch_bounds__(256, 1)
void k_rnn(const float* __restrict__ h0, const float* __restrict__ c0,
           const float* __restrict__ W_hh, float* __restrict__ out) {
    extern __shared__ float sm[];
    float* Wsh = sm;                                  // [64][516]
    float* hsh = sm + 64 * WS_STRIDE;                 // [16][524]
    float* red = hsh + 16 * HS_STRIDE;                // [8][64][16]

    int c = blockIdx.x, tid = threadIdx.x;
    int wid = tid >> 5, lane = tid & 31, gid = lane >> 2, tig = lane & 3;

    // cache W_hh slice (tf32-rounded) in smem
    for (int i = tid; i < 64 * HSZ; i += 256) {
        int lr = i >> 9, k = i & 511;
        int grow = (lr >> 4) * HSZ + c * 16 + (lr & 15);
        Wsh[lr * WS_STRIDE + k] = tf32r(W_hh[(size_t)grow * HSZ + k]);
    }

    int j = tid >> 4, b = tid & 15, dim = c * 16 + j; // pointwise ownership
    float creg = c0[b * HSZ + dim];

    for (int t = 0; t < TSZ; t++) {
        const float* hsrc = (t == 0) ? h0 : (d_hbuf + (t & 1) * (BSZ * HSZ));
        __syncthreads();
        // stage h (tf32-rounded), bypass L1 (rewritten by other CTAs)
        for (int i4 = tid; i4 < (BSZ * HSZ) / 4; i4 += 256) {
            int bb = i4 >> 7;
            int kk = (i4 & 127) * 4;
            float4 v = __ldcg((const float4*)(hsrc + bb * HSZ + kk));
            v.x = tf32r(v.x); v.y = tf32r(v.y); v.z = tf32r(v.z); v.w = tf32r(v.w);
            *(float4*)&hsh[bb * HS_STRIDE + kk] = v;
        }
        __syncthreads();

        // K-split MMA: warp wid handles k in [wid*64, wid*64+64)
        float acc[4][2][4];
#pragma unroll
        for (int mf = 0; mf < 4; mf++)
#pragma unroll
            for (int nf = 0; nf < 2; nf++)
#pragma unroll
                for (int r = 0; r < 4; r++) acc[mf][nf][r] = 0.f;
        int kbase = wid * 64;
#pragma unroll
        for (int kf = 0; kf < 8; kf++) {
            int k0 = kbase + kf * 8;
            uint32_t bfr[2][2];
            bfr[0][0] = fbits(hsh[gid * HS_STRIDE + k0 + tig]);
            bfr[0][1] = fbits(hsh[gid * HS_STRIDE + k0 + tig + 4]);
            bfr[1][0] = fbits(hsh[(8 + gid) * HS_STRIDE + k0 + tig]);
            bfr[1][1] = fbits(hsh[(8 + gid) * HS_STRIDE + k0 + tig + 4]);
#pragma unroll
            for (int mf = 0; mf < 4; mf++) {
                int m = mf * 16;
                uint32_t af[4];
                af[0] = fbits(Wsh[(m + gid)     * WS_STRIDE + k0 + tig]);
                af[1] = fbits(Wsh[(m + gid + 8) * WS_STRIDE + k0 + tig]);
                af[2] = fbits(Wsh[(m + gid)     * WS_STRIDE + k0 + tig + 4]);
                af[3] = fbits(Wsh[(m + gid + 8) * WS_STRIDE + k0 + tig + 4]);
                mma8(acc[mf][0], af, bfr[0]);
                mma8(acc[mf][1], af, bfr[1]);
            }
        }
        // dump partials for cross-warp K reduction
#pragma unroll
        for (int mf = 0; mf < 4; mf++)
#pragma unroll
            for (int nf = 0; nf < 2; nf++)
#pragma unroll
                for (int rg = 0; rg < 4; rg++) {
                    int lr = mf * 16 + gid + ((rg >= 2) ? 8 : 0);
                    int bb = nf * 8 + tig * 2 + (rg & 1);
                    red[(wid * 64 + lr) * 16 + bb] = acc[mf][nf][rg];
                }
        __syncthreads();

        // pointwise LSTM for (j, b)
        const float* xg = d_Xg + (size_t)(t * BSZ + b) * G4 + dim;
        float g[4];
#pragma unroll
        for (int q = 0; q < 4; q++) {
            float s = xg[q * HSZ];
            int lr = q * 16 + j;
#pragma unroll
            for (int w = 0; w < 8; w++) s += red[(w * 64 + lr) * 16 + b];
            g[q] = s;
        }
        float ig = sigf(g[0]), fg = sigf(g[1]), gg = tanhf(g[2]), og = sigf(g[3]);
        creg = fg * creg + ig * gg;
        float h2 = og * tanhf(creg);

        d_hbuf[((t + 1) & 1) * (BSZ * HSZ) + b * HSZ + dim] = h2;
        d_H2[(size_t)(t * BSZ + b) * HSZ + dim] = h2;
        if (t == TSZ - 1) {
            out[OUT_HF + b * HSZ + dim] = h2;
            out[OUT_CF + b * HSZ + dim] = creg;
        }

        __syncthreads();
        if (t < TSZ - 1) {
            if (tid == 0) {
                __threadfence();
                atomicAdd(&d_bar, 1u);
                unsigned target = 32u * (unsigned)(t + 1);
                unsigned v;
                do {
                    asm volatile("ld.global.acquire.gpu.u32 %0, [%1];"
                                 : "=r"(v) : "l"(&d_bar) : "memory");
                } while (v < target);
            }
            __syncthreads();
        }
    }
}

// ---------------- launch ----------------
extern "C" void kernel_launch(void* const* d_in, const int* in_sizes, int n_in,
                              void* d_out, int out_size) {
    (void)in_sizes; (void)n_in; (void)out_size;
    const float* h0    = (const float*)d_in[1];
    const float* c0    = (const float*)d_in[2];
    const void*  tgt   = d_in[3];
    const float* emb   = (const float*)d_in[4];
    const float* W_ih  = (const float*)d_in[5];
    const float* W_hh  = (const float*)d_in[6];
    const float* b_ih  = (const float*)d_in[7];
    const float* b_hh  = (const float*)d_in[8];
    const float* W_out = (const float*)d_in[9];
    const float* b_out = (const float*)d_in[10];
    float* out = (float*)d_out;

    cudaFuncSetAttribute(k_rnn, cudaFuncAttributeMaxDynamicSharedMemorySize, RNN_SMEM);

    k_prep<<<1, 256>>>(tgt);
    k_gather<<<NROW, 128>>>(emb);
    k_gemm<<<dim3(G4 / 128, NROW / 128), 256>>>(W_ih, b_ih, b_hh, nullptr, 0);
    k_rnn<<<32, 256, RNN_SMEM>>>(h0, c0, W_hh, out);
    k_gemm<<<dim3(VSZ / 128, NROW / 128), 256>>>(W_out, b_out, nullptr, out, 1);
}

// round 7
// speedup vs baseline: 1.1569x; 1.1569x over previous
#include <cuda_runtime.h>
#include <cstdint>

// Problem constants
#define VSZ   32000
#define HSZ   512
#define BSZ   16
#define TSZ   128
#define G4    2048           // 4*H
#define NROW  2048           // T*B rows
#define OUT_HF 65536000      // B*T*V
#define OUT_CF 65544192      // + B*H

#define NRNN   32            // recurrence CTAs
#define NCONS  116           // consumer CTAs
#define NGRID  (NRNN + NCONS)
#define NT     (VSZ / 128)   // 250 N-tiles
#define NCHUNK 16            // 16 chunks of 8 timesteps (128 rows each)
#define NJOBS  (NCHUNK * NT) // 4000

// ---------------- device scratch (no allocations allowed) ----------------
__device__ int      d_toks[NROW];
__device__ float    d_X [(size_t)NROW * HSZ];  // relu(emb[tok])       4 MB
__device__ float    d_Xg[(size_t)NROW * G4];   // X @ W_ih^T + b      16 MB
__device__ float    d_H2[(size_t)NROW * HSZ];  // all h2 states        4 MB
__device__ unsigned d_bar;                     // recurrence barrier counter
__device__ unsigned d_chunk;                   // published chunk count

// ---------------- helpers ----------------
__device__ __forceinline__ float tf32r(float x) {
    uint32_t u;
    asm("cvt.rna.tf32.f32 %0, %1;" : "=r"(u) : "f"(x));
    return __uint_as_float(u);
}
__device__ __forceinline__ uint32_t fbits(float x) { return __float_as_uint(x); }

__device__ __forceinline__ void mma8(float* d, const uint32_t* a, const uint32_t* b) {
    asm volatile(
        "mma.sync.aligned.m16n8k8.row.col.f32.tf32.tf32.f32 "
        "{%0,%1,%2,%3}, {%4,%5,%6,%7}, {%8,%9}, {%0,%1,%2,%3};"
        : "+f"(d[0]), "+f"(d[1]), "+f"(d[2]), "+f"(d[3])
        : "r"(a[0]), "r"(a[1]), "r"(a[2]), "r"(a[3]), "r"(b[0]), "r"(b[1]));
}

__device__ __forceinline__ float sigf(float x) { return 1.0f / (1.0f + __expf(-x)); }

__device__ __forceinline__ unsigned ld_acq(const unsigned* p) {
    unsigned v;
    asm volatile("ld.global.acquire.gpu.u32 %0, [%1];" : "=r"(v) : "l"(p) : "memory");
    return v;
}

// ---------------- kernel 0: token prep (+ dtype detect, + counter reset) ----
__global__ void k_prep(const void* tgt) {
    __shared__ int nz;
    if (threadIdx.x == 0) nz = 0;
    __syncthreads();
    const unsigned* w = (const unsigned*)tgt;
    for (int i = threadIdx.x; i < 1024; i += blockDim.x)
        if (w[2 * i + 1] != 0u) atomicOr(&nz, 1);
    __syncthreads();
    bool is64 = (nz == 0);
    const long long* p64 = (const long long*)tgt;
    const int*       p32 = (const int*)tgt;
    for (int idx = threadIdx.x; idx < NROW; idx += blockDim.x) {
        int t = idx >> 4, b = idx & 15;
        int tok;
        if (t == 0) tok = 1;                      // BOS
        else {
            int s = b * TSZ + (t - 1);
            tok = is64 ? (int)p64[s] : p32[s];
        }
        d_toks[idx] = tok;
    }
    if (threadIdx.x == 0) { d_bar = 0u; d_chunk = 0u; }
}

// ---------------- kernel 1: embedding gather + ReLU ----------------
__global__ void k_gather(const float* __restrict__ emb) {
    int r = blockIdx.x;
    int tok = d_toks[r];
    const float4* src = (const float4*)(emb + (size_t)tok * HSZ);
    float4*       dst = (float4*)(d_X + (size_t)r * HSZ);
    float4 v = src[threadIdx.x];
    v.x = fmaxf(v.x, 0.f); v.y = fmaxf(v.y, 0.f);
    v.z = fmaxf(v.z, 0.f); v.w = fmaxf(v.w, 0.f);
    dst[threadIdx.x] = v;
}

// ---------------- kernel 2: Xg = X @ W_ih^T + (b_ih + b_hh) ----------------
__global__ __launch_bounds__(256)
void k_gemm0(const float* __restrict__ Bmat, const float* __restrict__ bias1,
             const float* __restrict__ bias2) {
    __shared__ float As[128][20];
    __shared__ float Bs[128][20];

    const float* A = d_X;
    float*       C = d_Xg;
    const int    N = G4;

    int tM = blockIdx.y, tN = blockIdx.x;
    int tid = threadIdx.x;
    int wid = tid >> 5, lane = tid & 31;
    int gid = lane >> 2, tig = lane & 3;
    int wm = wid >> 2, wn = wid & 3;

    float acc[4][4][4];
#pragma unroll
    for (int i = 0; i < 4; i++)
#pragma unroll
        for (int j = 0; j < 4; j++)
#pragma unroll
            for (int k = 0; k < 4; k++) acc[i][j][k] = 0.f;

    int rowL = tid >> 1;
    int kseg = (tid & 1) * 8;
    const float* Ap = A    + (size_t)(tM * 128 + rowL) * HSZ + kseg;
    const float* Bp = Bmat + (size_t)(tN * 128 + rowL) * HSZ + kseg;

    float4 pa0 = *(const float4*)(Ap);
    float4 pa1 = *(const float4*)(Ap + 4);
    float4 pb0 = *(const float4*)(Bp);
    float4 pb1 = *(const float4*)(Bp + 4);

    for (int kk = 0; kk < HSZ; kk += 16) {
        __syncthreads();
        *(float4*)&As[rowL][kseg]     = make_float4(tf32r(pa0.x), tf32r(pa0.y), tf32r(pa0.z), tf32r(pa0.w));
        *(float4*)&As[rowL][kseg + 4] = make_float4(tf32r(pa1.x), tf32r(pa1.y), tf32r(pa1.z), tf32r(pa1.w));
        *(float4*)&Bs[rowL][kseg]     = make_float4(tf32r(pb0.x), tf32r(pb0.y), tf32r(pb0.z), tf32r(pb0.w));
        *(float4*)&Bs[rowL][kseg + 4] = make_float4(tf32r(pb1.x), tf32r(pb1.y), tf32r(pb1.z), tf32r(pb1.w));
        __syncthreads();
        if (kk + 16 < HSZ) {
            pa0 = *(const float4*)(Ap + kk + 16);
            pa1 = *(const float4*)(Ap + kk + 20);
            pb0 = *(const float4*)(Bp + kk + 16);
            pb1 = *(const float4*)(Bp + kk + 20);
        }
#pragma unroll
        for (int k8 = 0; k8 < 16; k8 += 8) {
            uint32_t af[4][4], bf[4][2];
#pragma unroll
            for (int mf = 0; mf < 4; mf++) {
                int m = wm * 64 + mf * 16;
                af[mf][0] = fbits(As[m + gid]    [k8 + tig]);
                af[mf][1] = fbits(As[m + gid + 8][k8 + tig]);
                af[mf][2] = fbits(As[m + gid]    [k8 + tig + 4]);
                af[mf][3] = fbits(As[m + gid + 8][k8 + tig + 4]);
            }
#pragma unroll
            for (int nf = 0; nf < 4; nf++) {
                int n = wn * 32 + nf * 8;
                bf[nf][0] = fbits(Bs[n + gid][k8 + tig]);
                bf[nf][1] = fbits(Bs[n + gid][k8 + tig + 4]);
            }
#pragma unroll
            for (int mf = 0; mf < 4; mf++)
#pragma unroll
                for (int nf = 0; nf < 4; nf++) mma8(acc[mf][nf], af[mf], bf[nf]);
        }
    }

#pragma unroll
    for (int mf = 0; mf < 4; mf++) {
        int r0 = tM * 128 + wm * 64 + mf * 16 + gid;
        int r1 = r0 + 8;
#pragma unroll
        for (int nf = 0; nf < 4; nf++) {
            int cn = tN * 128 + wn * 32 + nf * 8 + tig * 2;
            float bv0 = bias1[cn] + bias2[cn];
            float bv1 = bias1[cn + 1] + bias2[cn + 1];
            *(float2*)(C + (size_t)r0 * N + cn) = make_float2(acc[mf][nf][0] + bv0, acc[mf][nf][1] + bv1);
            *(float2*)(C + (size_t)r1 * N + cn) = make_float2(acc[mf][nf][2] + bv0, acc[mf][nf][3] + bv1);
        }
    }
}

// ================== fused persistent kernel ==================
#define WS_STRIDE 516
#define HS_STRIDE 524
#define RNN_SMEM ((64 * WS_STRIDE + 16 * HS_STRIDE + 8 * 64 * 16) * 4)
#define GSTR 36   // consumer smem row stride (floats)

// ---- consumer: one 128x128 logits tile, double-buffered K=32 stages ----
__device__ void gemm_tile_logits(float* sm, const float* __restrict__ Wout,
                                 const float* __restrict__ bout,
                                 float* __restrict__ out, int chunk, int ntile) {
    float* Abuf = sm;                      // [2][128*GSTR]
    float* Bbuf = sm + 2 * 128 * GSTR;     // [2][128*GSTR]

    int tid = threadIdx.x;
    int wid = tid >> 5, lane = tid & 31, gid = lane >> 2, tig = lane & 3;
    int wm = wid >> 2, wn = wid & 3;

    int lrow = tid >> 1;
    int lcol = (tid & 1) * 16;
    const float* Ap = d_H2 + (size_t)(chunk * 128 + lrow) * HSZ + lcol;
    const float* Bp = Wout + (size_t)(ntile * 128 + lrow) * HSZ + lcol;

    float4 ra[4], rb[4];
#pragma unroll
    for (int i = 0; i < 4; i++) {
        ra[i] = __ldcg((const float4*)(Ap + i * 4));
        rb[i] = __ldg((const float4*)(Bp + i * 4));
    }

    float acc[4][4][4];
#pragma unroll
    for (int i = 0; i < 4; i++)
#pragma unroll
        for (int j = 0; j < 4; j++)
#pragma unroll
            for (int k = 0; k < 4; k++) acc[i][j][k] = 0.f;

    // stage 0 -> buf 0
    {
        float* as = Abuf + lrow * GSTR + lcol;
        float* bs = Bbuf + lrow * GSTR + lcol;
#pragma unroll
        for (int i = 0; i < 4; i++) {
            *(float4*)(as + i * 4) = make_float4(tf32r(ra[i].x), tf32r(ra[i].y), tf32r(ra[i].z), tf32r(ra[i].w));
            *(float4*)(bs + i * 4) = make_float4(tf32r(rb[i].x), tf32r(rb[i].y), tf32r(rb[i].z), tf32r(rb[i].w));
        }
    }
    __syncthreads();

    for (int s = 0; s < 16; s++) {
        if (s < 15) {
            int k0 = (s + 1) * 32;
#pragma unroll
            for (int i = 0; i < 4; i++) {
                ra[i] = __ldcg((const float4*)(Ap + k0 + i * 4));
                rb[i] = __ldg((const float4*)(Bp + k0 + i * 4));
            }
        }
        const float* asb = Abuf + (s & 1) * 128 * GSTR;
        const float* bsb = Bbuf + (s & 1) * 128 * GSTR;
#pragma unroll
        for (int k8 = 0; k8 < 32; k8 += 8) {
            uint32_t af[4][4], bf[4][2];
#pragma unroll
            for (int mf = 0; mf < 4; mf++) {
                int m = wm * 64 + mf * 16;
                af[mf][0] = fbits(asb[(m + gid)     * GSTR + k8 + tig]);
                af[mf][1] = fbits(asb[(m + gid + 8) * GSTR + k8 + tig]);
                af[mf][2] = fbits(asb[(m + gid)     * GSTR + k8 + tig + 4]);
                af[mf][3] = fbits(asb[(m + gid + 8) * GSTR + k8 + tig + 4]);
            }
#pragma unroll
            for (int nf = 0; nf < 4; nf++) {
                int n = wn * 32 + nf * 8;
                bf[nf][0] = fbits(bsb[(n + gid) * GSTR + k8 + tig]);
                bf[nf][1] = fbits(bsb[(n + gid) * GSTR + k8 + tig + 4]);
            }
#pragma unroll
            for (int mf = 0; mf < 4; mf++)
#pragma unroll
                for (int nf = 0; nf < 4; nf++) mma8(acc[mf][nf], af[mf], bf[nf]);
        }
        if (s < 15) {
            __syncthreads();
            float* as = Abuf + ((s + 1) & 1) * 128 * GSTR + lrow * GSTR + lcol;
            float* bs = Bbuf + ((s + 1) & 1) * 128 * GSTR + lrow * GSTR + lcol;
#pragma unroll
            for (int i = 0; i < 4; i++) {
                *(float4*)(as + i * 4) = make_float4(tf32r(ra[i].x), tf32r(ra[i].y), tf32r(ra[i].z), tf32r(ra[i].w));
                *(float4*)(bs + i * 4) = make_float4(tf32r(rb[i].x), tf32r(rb[i].y), tf32r(rb[i].z), tf32r(rb[i].w));
            }
            __syncthreads();
        }
    }

    // epilogue: row r = t*B+b  ->  out row b*T+t
#pragma unroll
    for (int mf = 0; mf < 4; mf++) {
        int r0 = chunk * 128 + wm * 64 + mf * 16 + gid;
        int r1 = r0 + 8;
        int o0 = (r0 & 15) * TSZ + (r0 >> 4);
        int o1 = (r1 & 15) * TSZ + (r1 >> 4);
#pragma unroll
        for (int nf = 0; nf < 4; nf++) {
            int cn = ntile * 128 + wn * 32 + nf * 8 + tig * 2;
            float bv0 = bout[cn], bv1 = bout[cn + 1];
            *(float2*)(out + (size_t)o0 * VSZ + cn) = make_float2(acc[mf][nf][0] + bv0, acc[mf][nf][1] + bv1);
            *(float2*)(out + (size_t)o1 * VSZ + cn) = make_float2(acc[mf][nf][2] + bv0, acc[mf][nf][3] + bv1);
        }
    }
}

__global__ __launch_bounds__(256, 1)
void k_fused(const float* __restrict__ h0, const float* __restrict__ c0,
             const float* __restrict__ W_hh, const float* __restrict__ W_out,
             const float* __restrict__ b_out, float* __restrict__ out) {
    extern __shared__ float sm[];
    int tid = threadIdx.x;

    if (blockIdx.x >= NRNN) {
        // -------- consumer role: logits GEMM chunks as they are published -----
        int cidx = blockIdx.x - NRNN;
        for (int j = cidx; j < NJOBS; j += NCONS) {
            int chunk = j / NT, ntile = j % NT;
            if (tid == 0) {
                while (ld_acq(&d_chunk) <= (unsigned)chunk) __nanosleep(256);
            }
            __syncthreads();
            gemm_tile_logits(sm, W_out, b_out, out, chunk, ntile);
            __syncthreads();
        }
        return;
    }

    // -------- recurrence role (32 CTAs) --------
    float* Wsh = sm;                                  // [64][516]
    float* hsh = sm + 64 * WS_STRIDE;                 // [16][524]
    float* red = hsh + 16 * HS_STRIDE;                // [8][64][16]

    int c = blockIdx.x;
    int wid = tid >> 5, lane = tid & 31, gid = lane >> 2, tig = lane & 3;

    for (int i = tid; i < 64 * HSZ; i += 256) {
        int lr = i >> 9, k = i & 511;
        int grow = (lr >> 4) * HSZ + c * 16 + (lr & 15);
        Wsh[lr * WS_STRIDE + k] = tf32r(W_hh[(size_t)grow * HSZ + k]);
    }

    int j = tid >> 4, b = tid & 15, dim = c * 16 + j;
    float creg = c0[b * HSZ + dim];

    for (int t = 0; t < TSZ; t++) {
        const float* hsrc = (t == 0) ? h0 : (d_H2 + (size_t)(t - 1) * (BSZ * HSZ));
        __syncthreads();
        for (int i4 = tid; i4 < (BSZ * HSZ) / 4; i4 += 256) {
            int bb = i4 >> 7;
            int kk = (i4 & 127) * 4;
            float4 v = __ldcg((const float4*)(hsrc + bb * HSZ + kk));
            v.x = tf32r(v.x); v.y = tf32r(v.y); v.z = tf32r(v.z); v.w = tf32r(v.w);
            *(float4*)&hsh[bb * HS_STRIDE + kk] = v;
        }
        __syncthreads();

        float acc[4][2][4];
#pragma unroll
        for (int mf = 0; mf < 4; mf++)
#pragma unroll
            for (int nf = 0; nf < 2; nf++)
#pragma unroll
                for (int r = 0; r < 4; r++) acc[mf][nf][r] = 0.f;
        int kbase = wid * 64;
#pragma unroll
        for (int kf = 0; kf < 8; kf++) {
            int k0 = kbase + kf * 8;
            uint32_t bfr[2][2];
            bfr[0][0] = fbits(hsh[gid * HS_STRIDE + k0 + tig]);
            bfr[0][1] = fbits(hsh[gid * HS_STRIDE + k0 + tig + 4]);
            bfr[1][0] = fbits(hsh[(8 + gid) * HS_STRIDE + k0 + tig]);
            bfr[1][1] = fbits(hsh[(8 + gid) * HS_STRIDE + k0 + tig + 4]);
#pragma unroll
            for (int mf = 0; mf < 4; mf++) {
                int m = mf * 16;
                uint32_t af[4];
                af[0] = fbits(Wsh[(m + gid)     * WS_STRIDE + k0 + tig]);
                af[1] = fbits(Wsh[(m + gid + 8) * WS_STRIDE + k0 + tig]);
                af[2] = fbits(Wsh[(m + gid)     * WS_STRIDE + k0 + tig + 4]);
                af[3] = fbits(Wsh[(m + gid + 8) * WS_STRIDE + k0 + tig + 4]);
                mma8(acc[mf][0], af, bfr[0]);
                mma8(acc[mf][1], af, bfr[1]);
            }
        }
#pragma unroll
        for (int mf = 0; mf < 4; mf++)
#pragma unroll
            for (int nf = 0; nf < 2; nf++)
#pragma unroll
                for (int rg = 0; rg < 4; rg++) {
                    int lr = mf * 16 + gid + ((rg >= 2) ? 8 : 0);
                    int bb = nf * 8 + tig * 2 + (rg & 1);
                    red[(wid * 64 + lr) * 16 + bb] = acc[mf][nf][rg];
                }
        __syncthreads();

        const float* xg = d_Xg + (size_t)(t * BSZ + b) * G4 + dim;
        float g[4];
#pragma unroll
        for (int q = 0; q < 4; q++) {
            float s = xg[q * HSZ];
            int lr = q * 16 + j;
#pragma unroll
            for (int w = 0; w < 8; w++) s += red[(w * 64 + lr) * 16 + b];
            g[q] = s;
        }
        float ig = sigf(g[0]), fg = sigf(g[1]), gg = tanhf(g[2]), og = sigf(g[3]);
        creg = fg * creg + ig * gg;
        float h2 = og * tanhf(creg);

        d_H2[(size_t)(t * BSZ + b) * HSZ + dim] = h2;
        if (t == TSZ - 1) {
            out[OUT_HF + b * HSZ + dim] = h2;
            out[OUT_CF + b * HSZ + dim] = creg;
        }

        __syncthreads();
        if (t < TSZ - 1) {
            if (tid == 0) {
                __threadfence();
                atomicAdd(&d_bar, 1u);
                unsigned target = 32u * (unsigned)(t + 1);
                while (ld_acq(&d_bar) < target) { }
                if (c == 0 && ((t + 1) & 7) == 0) {
                    __threadfence();
                    *(volatile unsigned*)&d_chunk = (unsigned)((t + 1) >> 3);
                }
            }
            __syncthreads();
        }
    }

    // final step publication (chunk 15)
    if (tid == 0) {
        __threadfence();
        atomicAdd(&d_bar, 1u);
        if (c == 0) {
            while (ld_acq(&d_bar) < 32u * TSZ) { }
            __threadfence();
            *(volatile unsigned*)&d_chunk = NCHUNK;
        }
    }
}

// ---------------- launch ----------------
extern "C" void kernel_launch(void* const* d_in, const int* in_sizes, int n_in,
                              void* d_out, int out_size) {
    (void)in_sizes; (void)n_in; (void)out_size;
    const float* h0    = (const float*)d_in[1];
    const float* c0    = (const float*)d_in[2];
    const void*  tgt   = d_in[3];
    const float* emb   = (const float*)d_in[4];
    const float* W_ih  = (const float*)d_in[5];
    const float* W_hh  = (const float*)d_in[6];
    const float* b_ih  = (const float*)d_in[7];
    const float* b_hh  = (const float*)d_in[8];
    const float* W_out = (const float*)d_in[9];
    const float* b_out = (const float*)d_in[10];
    float* out = (float*)d_out;

    cudaFuncSetAttribute(k_fused, cudaFuncAttributeMaxDynamicSharedMemorySize, RNN_SMEM);

    k_prep<<<1, 256>>>(tgt);
    k_gather<<<NROW, 128>>>(emb);
    k_gemm0<<<dim3(G4 / 128, NROW / 128), 256>>>(W_ih, b_ih, b_hh);
    k_fused<<<NGRID, 256, RNN_SMEM>>>(h0, c0, W_hh, W_out, b_out, out);
}

// round 8
// speedup vs baseline: 1.3534x; 1.1699x over previous
#include <cuda_runtime.h>
#include <cstdint>

// Problem constants
#define VSZ   32000
#define HSZ   512
#define BSZ   16
#define TSZ   128
#define G4    2048           // 4*H
#define NROW  2048           // T*B rows
#define OUT_HF 65536000      // B*T*V
#define OUT_CF 65544192      // + B*H

#define NRNN   32            // recurrence CTAs
#define NCONS  116           // consumer CTAs
#define NGRID  (NRNN + NCONS)
#define NT     (VSZ / 128)   // 250 N-tiles
#define NCHUNK 16            // 16 chunks of 8 timesteps (128 rows each)
#define NJOBS  (NCHUNK * NT) // 4000

// ---------------- device scratch (no allocations allowed) ----------------
__device__ int      d_toks[NROW];
__device__ float    d_X [(size_t)NROW * HSZ];  // relu(emb[tok])       4 MB
__device__ float    d_Xg[(size_t)NROW * G4];   // X @ W_ih^T + b      16 MB
__device__ float    d_H2[(size_t)NROW * HSZ];  // all h2 (tf32-rounded) 4 MB
__device__ unsigned d_bar;                     // recurrence barrier counter
__device__ unsigned d_chunk;                   // published chunk count

// ---------------- helpers ----------------
__device__ __forceinline__ float tf32r(float x) {
    uint32_t u;
    asm("cvt.rna.tf32.f32 %0, %1;" : "=r"(u) : "f"(x));
    return __uint_as_float(u);
}
__device__ __forceinline__ uint32_t fbits(float x) { return __float_as_uint(x); }
__device__ __forceinline__ uint32_t s2u(const void* p) {
    return (uint32_t)__cvta_generic_to_shared(p);
}

__device__ __forceinline__ void mma8(float* d, const uint32_t* a, const uint32_t* b) {
    asm volatile(
        "mma.sync.aligned.m16n8k8.row.col.f32.tf32.tf32.f32 "
        "{%0,%1,%2,%3}, {%4,%5,%6,%7}, {%8,%9}, {%0,%1,%2,%3};"
        : "+f"(d[0]), "+f"(d[1]), "+f"(d[2]), "+f"(d[3])
        : "r"(a[0]), "r"(a[1]), "r"(a[2]), "r"(a[3]), "r"(b[0]), "r"(b[1]));
}

__device__ __forceinline__ void ldsm4(uint32_t* r, uint32_t addr) {
    asm volatile("ldmatrix.sync.aligned.m8n8.x4.shared.b16 {%0,%1,%2,%3}, [%4];"
                 : "=r"(r[0]), "=r"(r[1]), "=r"(r[2]), "=r"(r[3]) : "r"(addr));
}

__device__ __forceinline__ float sigf(float x) { return 1.0f / (1.0f + __expf(-x)); }

__device__ __forceinline__ unsigned ld_acq(const unsigned* p) {
    unsigned v;
    asm volatile("ld.global.acquire.gpu.u32 %0, [%1];" : "=r"(v) : "l"(p) : "memory");
    return v;
}

// ---------------- kernel 0: token prep (+ dtype detect, + counter reset) ----
__global__ void k_prep(const void* tgt) {
    __shared__ int nz;
    if (threadIdx.x == 0) nz = 0;
    __syncthreads();
    const unsigned* w = (const unsigned*)tgt;
    for (int i = threadIdx.x; i < 1024; i += blockDim.x)
        if (w[2 * i + 1] != 0u) atomicOr(&nz, 1);
    __syncthreads();
    bool is64 = (nz == 0);
    const long long* p64 = (const long long*)tgt;
    const int*       p32 = (const int*)tgt;
    for (int idx = threadIdx.x; idx < NROW; idx += blockDim.x) {
        int t = idx >> 4, b = idx & 15;
        int tok;
        if (t == 0) tok = 1;                      // BOS
        else {
            int s = b * TSZ + (t - 1);
            tok = is64 ? (int)p64[s] : p32[s];
        }
        d_toks[idx] = tok;
    }
    if (threadIdx.x == 0) { d_bar = 0u; d_chunk = 0u; }
}

// ---------------- kernel 1: embedding gather + ReLU ----------------
__global__ void k_gather(const float* __restrict__ emb) {
    int r = blockIdx.x;
    int tok = d_toks[r];
    const float4* src = (const float4*)(emb + (size_t)tok * HSZ);
    float4*       dst = (float4*)(d_X + (size_t)r * HSZ);
    float4 v = src[threadIdx.x];
    v.x = fmaxf(v.x, 0.f); v.y = fmaxf(v.y, 0.f);
    v.z = fmaxf(v.z, 0.f); v.w = fmaxf(v.w, 0.f);
    dst[threadIdx.x] = v;
}

// ---------------- kernel 2: Xg = X @ W_ih^T + (b_ih + b_hh) ----------------
__global__ __launch_bounds__(256)
void k_gemm0(const float* __restrict__ Bmat, const float* __restrict__ bias1,
             const float* __restrict__ bias2) {
    __shared__ float As[128][20];
    __shared__ float Bs[128][20];

    const float* A = d_X;
    float*       C = d_Xg;
    const int    N = G4;

    int tM = blockIdx.y, tN = blockIdx.x;
    int tid = threadIdx.x;
    int wid = tid >> 5, lane = tid & 31;
    int gid = lane >> 2, tig = lane & 3;
    int wm = wid >> 2, wn = wid & 3;

    float acc[4][4][4];
#pragma unroll
    for (int i = 0; i < 4; i++)
#pragma unroll
        for (int j = 0; j < 4; j++)
#pragma unroll
            for (int k = 0; k < 4; k++) acc[i][j][k] = 0.f;

    int rowL = tid >> 1;
    int kseg = (tid & 1) * 8;
    const float* Ap = A    + (size_t)(tM * 128 + rowL) * HSZ + kseg;
    const float* Bp = Bmat + (size_t)(tN * 128 + rowL) * HSZ + kseg;

    float4 pa0 = *(const float4*)(Ap);
    float4 pa1 = *(const float4*)(Ap + 4);
    float4 pb0 = *(const float4*)(Bp);
    float4 pb1 = *(const float4*)(Bp + 4);

    for (int kk = 0; kk < HSZ; kk += 16) {
        __syncthreads();
        *(float4*)&As[rowL][kseg]     = make_float4(tf32r(pa0.x), tf32r(pa0.y), tf32r(pa0.z), tf32r(pa0.w));
        *(float4*)&As[rowL][kseg + 4] = make_float4(tf32r(pa1.x), tf32r(pa1.y), tf32r(pa1.z), tf32r(pa1.w));
        *(float4*)&Bs[rowL][kseg]     = make_float4(tf32r(pb0.x), tf32r(pb0.y), tf32r(pb0.z), tf32r(pb0.w));
        *(float4*)&Bs[rowL][kseg + 4] = make_float4(tf32r(pb1.x), tf32r(pb1.y), tf32r(pb1.z), tf32r(pb1.w));
        __syncthreads();
        if (kk + 16 < HSZ) {
            pa0 = *(const float4*)(Ap + kk + 16);
            pa1 = *(const float4*)(Ap + kk + 20);
            pb0 = *(const float4*)(Bp + kk + 16);
            pb1 = *(const float4*)(Bp + kk + 20);
        }
#pragma unroll
        for (int k8 = 0; k8 < 16; k8 += 8) {
            uint32_t af[4][4], bf[4][2];
#pragma unroll
            for (int mf = 0; mf < 4; mf++) {
                int m = wm * 64 + mf * 16;
                af[mf][0] = fbits(As[m + gid]    [k8 + tig]);
                af[mf][1] = fbits(As[m + gid + 8][k8 + tig]);
                af[mf][2] = fbits(As[m + gid]    [k8 + tig + 4]);
                af[mf][3] = fbits(As[m + gid + 8][k8 + tig + 4]);
            }
#pragma unroll
            for (int nf = 0; nf < 4; nf++) {
                int n = wn * 32 + nf * 8;
                bf[nf][0] = fbits(Bs[n + gid][k8 + tig]);
                bf[nf][1] = fbits(Bs[n + gid][k8 + tig + 4]);
            }
#pragma unroll
            for (int mf = 0; mf < 4; mf++)
#pragma unroll
                for (int nf = 0; nf < 4; nf++) mma8(acc[mf][nf], af[mf], bf[nf]);
        }
    }

#pragma unroll
    for (int mf = 0; mf < 4; mf++) {
        int r0 = tM * 128 + wm * 64 + mf * 16 + gid;
        int r1 = r0 + 8;
#pragma unroll
        for (int nf = 0; nf < 4; nf++) {
            int cn = tN * 128 + wn * 32 + nf * 8 + tig * 2;
            float bv0 = bias1[cn] + bias2[cn];
            float bv1 = bias1[cn + 1] + bias2[cn + 1];
            *(float2*)(C + (size_t)r0 * N + cn) = make_float2(acc[mf][nf][0] + bv0, acc[mf][nf][1] + bv1);
            *(float2*)(C + (size_t)r1 * N + cn) = make_float2(acc[mf][nf][2] + bv0, acc[mf][nf][3] + bv1);
        }
    }
}

// ================== fused persistent kernel ==================
#define WS_STRIDE 516
#define HS_STRIDE 524
#define RNN_SMEM ((64 * WS_STRIDE + 16 * HS_STRIDE + 8 * 64 * 16) * 4)
#define GSTR 36   // consumer smem row stride (floats)

// ---- consumer: one 128x128 logits tile, double-buffered, ldmatrix frags ----
__device__ void gemm_tile_logits(float* sm, const float* __restrict__ Wout,
                                 const float* __restrict__ bout,
                                 float* __restrict__ out, int chunk, int ntile) {
    float* Abuf = sm;                      // [2][128*GSTR]
    float* Bbuf = sm + 2 * 128 * GSTR;     // [2][128*GSTR]

    int tid = threadIdx.x;
    int wid = tid >> 5, lane = tid & 31;
    int wm = wid >> 2, wn = wid & 3;
    int r8 = lane & 7, sq = lane >> 3;

    // ldmatrix per-lane offsets (bytes)
    uint32_t a_off = (uint32_t)((((sq & 1) * 8 + r8) * GSTR + (sq >> 1) * 4) * 4);
    uint32_t b_off = (uint32_t)((((sq >> 1) * 8 + r8) * GSTR + (sq & 1) * 4) * 4);
    uint32_t abase0 = s2u(Abuf) + (uint32_t)(wm * 64 * GSTR * 4) + a_off;
    uint32_t bbase0 = s2u(Bbuf) + (uint32_t)(wn * 32 * GSTR * 4) + b_off;

    int lrow = tid >> 1;
    int lcol = (tid & 1) * 16;
    const float* Ap = d_H2 + (size_t)(chunk * 128 + lrow) * HSZ + lcol;
    const float* Bp = Wout + (size_t)(ntile * 128 + lrow) * HSZ + lcol;

    float4 ra[4], rb[4];
#pragma unroll
    for (int i = 0; i < 4; i++) {
        ra[i] = __ldcg((const float4*)(Ap + i * 4));   // already tf32-rounded
        rb[i] = __ldg((const float4*)(Bp + i * 4));
    }

    float acc[4][4][4];
#pragma unroll
    for (int i = 0; i < 4; i++)
#pragma unroll
        for (int j = 0; j < 4; j++)
#pragma unroll
            for (int k = 0; k < 4; k++) acc[i][j][k] = 0.f;

    // stage 0 -> buf 0
    {
        float* as = Abuf + lrow * GSTR + lcol;
        float* bs = Bbuf + lrow * GSTR + lcol;
#pragma unroll
        for (int i = 0; i < 4; i++) {
            *(float4*)(as + i * 4) = ra[i];
            *(float4*)(bs + i * 4) = make_float4(tf32r(rb[i].x), tf32r(rb[i].y), tf32r(rb[i].z), tf32r(rb[i].w));
        }
    }
    __syncthreads();

    for (int s = 0; s < 16; s++) {
        if (s < 15) {
            int k0 = (s + 1) * 32;
#pragma unroll
            for (int i = 0; i < 4; i++) {
                ra[i] = __ldcg((const float4*)(Ap + k0 + i * 4));
                rb[i] = __ldg((const float4*)(Bp + k0 + i * 4));
            }
        }
        uint32_t asb = abase0 + (uint32_t)((s & 1) * 128 * GSTR * 4);
        uint32_t bsb = bbase0 + (uint32_t)((s & 1) * 128 * GSTR * 4);
#pragma unroll
        for (int k8 = 0; k8 < 32; k8 += 8) {
            uint32_t af[4][4], bf[2][4];
#pragma unroll
            for (int mf = 0; mf < 4; mf++)
                ldsm4(af[mf], asb + (uint32_t)(mf * 16 * GSTR * 4) + (uint32_t)(k8 * 4));
            ldsm4(bf[0], bsb + (uint32_t)(k8 * 4));
            ldsm4(bf[1], bsb + (uint32_t)(16 * GSTR * 4) + (uint32_t)(k8 * 4));
#pragma unroll
            for (int mf = 0; mf < 4; mf++) {
                mma8(acc[mf][0], af[mf], &bf[0][0]);
                mma8(acc[mf][1], af[mf], &bf[0][2]);
                mma8(acc[mf][2], af[mf], &bf[1][0]);
                mma8(acc[mf][3], af[mf], &bf[1][2]);
            }
        }
        if (s < 15) {
            __syncthreads();
            float* as = Abuf + ((s + 1) & 1) * 128 * GSTR + lrow * GSTR + lcol;
            float* bs = Bbuf + ((s + 1) & 1) * 128 * GSTR + lrow * GSTR + lcol;
#pragma unroll
            for (int i = 0; i < 4; i++) {
                *(float4*)(as + i * 4) = ra[i];
                *(float4*)(bs + i * 4) = make_float4(tf32r(rb[i].x), tf32r(rb[i].y), tf32r(rb[i].z), tf32r(rb[i].w));
            }
            __syncthreads();
        }
    }

    // epilogue: row r = t*B+b  ->  out row b*T+t
    int gid = lane >> 2, tig = lane & 3;
#pragma unroll
    for (int mf = 0; mf < 4; mf++) {
        int r0 = chunk * 128 + wm * 64 + mf * 16 + gid;
        int r1 = r0 + 8;
        int o0 = (r0 & 15) * TSZ + (r0 >> 4);
        int o1 = (r1 & 15) * TSZ + (r1 >> 4);
#pragma unroll
        for (int nf = 0; nf < 4; nf++) {
            int cn = ntile * 128 + wn * 32 + nf * 8 + tig * 2;
            float bv0 = bout[cn], bv1 = bout[cn + 1];
            *(float2*)(out + (size_t)o0 * VSZ + cn) = make_float2(acc[mf][nf][0] + bv0, acc[mf][nf][1] + bv1);
            *(float2*)(out + (size_t)o1 * VSZ + cn) = make_float2(acc[mf][nf][2] + bv0, acc[mf][nf][3] + bv1);
        }
    }
}

__global__ __launch_bounds__(256, 1)
void k_fused(const float* __restrict__ h0, const float* __restrict__ c0,
             const float* __restrict__ W_hh, const float* __restrict__ W_out,
             const float* __restrict__ b_out, float* __restrict__ out) {
    extern __shared__ float sm[];
    int tid = threadIdx.x;

    if (blockIdx.x >= NRNN) {
        // -------- consumer role --------
        int cidx = blockIdx.x - NRNN;
        for (int j = cidx; j < NJOBS; j += NCONS) {
            int chunk = j / NT, ntile = j % NT;
            if (tid == 0) {
                while (ld_acq(&d_chunk) <= (unsigned)chunk) __nanosleep(128);
            }
            __syncthreads();
            gemm_tile_logits(sm, W_out, b_out, out, chunk, ntile);
            __syncthreads();
        }
        return;
    }

    // -------- recurrence role (32 CTAs) --------
    float* Wsh = sm;                                  // [64][516]
    float* hsh = sm + 64 * WS_STRIDE;                 // [16][524]
    float* red = hsh + 16 * HS_STRIDE;                // [8][64][16]

    int c = blockIdx.x;
    int wid = tid >> 5, lane = tid & 31, gid = lane >> 2, tig = lane & 3;
    int r8 = lane & 7, sq = lane >> 3;

    uint32_t w_off = (uint32_t)((((sq & 1) * 8 + r8) * WS_STRIDE + (sq >> 1) * 4) * 4);
    uint32_t h_off = (uint32_t)((((sq >> 1) * 8 + r8) * HS_STRIDE + (sq & 1) * 4) * 4);
    uint32_t wbase = s2u(Wsh) + w_off;
    uint32_t hbase = s2u(hsh) + h_off;

    for (int i = tid; i < 64 * HSZ; i += 256) {
        int lr = i >> 9, k = i & 511;
        int grow = (lr >> 4) * HSZ + c * 16 + (lr & 15);
        Wsh[lr * WS_STRIDE + k] = tf32r(W_hh[(size_t)grow * HSZ + k]);
    }

    int j = tid >> 4, b = tid & 15, dim = c * 16 + j;
    float creg = c0[b * HSZ + dim];

    for (int t = 0; t < TSZ; t++) {
        const float* hsrc = (t == 0) ? h0 : (d_H2 + (size_t)(t - 1) * (BSZ * HSZ));
        // prefetch gate pre-activations (DRAM) for this step early
        const float* xg = d_Xg + (size_t)(t * BSZ + b) * G4 + dim;
        float gx0 = __ldcs(xg);
        float gx1 = __ldcs(xg + HSZ);
        float gx2 = __ldcs(xg + 2 * HSZ);
        float gx3 = __ldcs(xg + 3 * HSZ);

        __syncthreads();
        // stage h (tf32 rounding is idempotent for t>0; needed for t==0)
        for (int i4 = tid; i4 < (BSZ * HSZ) / 4; i4 += 256) {
            int bb = i4 >> 7;
            int kk = (i4 & 127) * 4;
            float4 v = __ldcg((const float4*)(hsrc + bb * HSZ + kk));
            v.x = tf32r(v.x); v.y = tf32r(v.y); v.z = tf32r(v.z); v.w = tf32r(v.w);
            *(float4*)&hsh[bb * HS_STRIDE + kk] = v;
        }
        __syncthreads();

        // K-split MMA: warp wid handles k in [wid*64, wid*64+64)
        float acc[4][2][4];
#pragma unroll
        for (int mf = 0; mf < 4; mf++)
#pragma unroll
            for (int nf = 0; nf < 2; nf++)
#pragma unroll
                for (int r = 0; r < 4; r++) acc[mf][nf][r] = 0.f;
        int kbase = wid * 64;
#pragma unroll
        for (int kf = 0; kf < 8; kf++) {
            int k0 = kbase + kf * 8;
            uint32_t bfr[4], af[4];
            ldsm4(bfr, hbase + (uint32_t)(k0 * 4));
#pragma unroll
            for (int mf = 0; mf < 4; mf++) {
                ldsm4(af, wbase + (uint32_t)((mf * 16 * WS_STRIDE + k0) * 4));
                mma8(acc[mf][0], af, &bfr[0]);
                mma8(acc[mf][1], af, &bfr[2]);
            }
        }
#pragma unroll
        for (int mf = 0; mf < 4; mf++)
#pragma unroll
            for (int nf = 0; nf < 2; nf++)
#pragma unroll
                for (int rg = 0; rg < 4; rg++) {
                    int lr = mf * 16 + gid + ((rg >= 2) ? 8 : 0);
                    int bb = nf * 8 + tig * 2 + (rg & 1);
                    red[(wid * 64 + lr) * 16 + bb] = acc[mf][nf][rg];
                }
        __syncthreads();

        float g[4] = {gx0, gx1, gx2, gx3};
#pragma unroll
        for (int q = 0; q < 4; q++) {
            int lr = q * 16 + j;
#pragma unroll
            for (int w = 0; w < 8; w++) g[q] += red[(w * 64 + lr) * 16 + b];
        }
        float ig = sigf(g[0]), fg = sigf(g[1]), gg = tanhf(g[2]), og = sigf(g[3]);
        creg = fg * creg + ig * gg;
        float h2 = og * tanhf(creg);

        // store tf32-rounded h2 (both consumers round anyway -> identical math)
        d_H2[(size_t)(t * BSZ + b) * HSZ + dim] = tf32r(h2);
        if (t == TSZ - 1) {
            out[OUT_HF + b * HSZ + dim] = h2;     // exact final states
            out[OUT_CF + b * HSZ + dim] = creg;
        }

        __syncthreads();
        if (t < TSZ - 1) {
            if (tid == 0) {
                __threadfence();
                atomicAdd(&d_bar, 1u);
                unsigned target = 32u * (unsigned)(t + 1);
                while (ld_acq(&d_bar) < target) { }
                if (c == 0 && ((t + 1) & 7) == 0) {
                    __threadfence();
                    *(volatile unsigned*)&d_chunk = (unsigned)((t + 1) >> 3);
                }
            }
            __syncthreads();
        }
    }

    // final chunk publication
    if (tid == 0) {
        __threadfence();
        atomicAdd(&d_bar, 1u);
        if (c == 0) {
            while (ld_acq(&d_bar) < 32u * TSZ) { }
            __threadfence();
            *(volatile unsigned*)&d_chunk = NCHUNK;
        }
    }
}

// ---------------- launch ----------------
extern "C" void kernel_launch(void* const* d_in, const int* in_sizes, int n_in,
                              void* d_out, int out_size) {
    (void)in_sizes; (void)n_in; (void)out_size;
    const float* h0    = (const float*)d_in[1];
    const float* c0    = (const float*)d_in[2];
    const void*  tgt   = d_in[3];
    const float* emb   = (const float*)d_in[4];
    const float* W_ih  = (const float*)d_in[5];
    const float* W_hh  = (const float*)d_in[6];
    const float* b_ih  = (const float*)d_in[7];
    const float* b_hh  = (const float*)d_in[8];
    const float* W_out = (const float*)d_in[9];
    const float* b_out = (const float*)d_in[10];
    float* out = (float*)d_out;

    cudaFuncSetAttribute(k_fused, cudaFuncAttributeMaxDynamicSharedMemorySize, RNN_SMEM);

    k_prep<<<1, 256>>>(tgt);
    k_gather<<<NROW, 128>>>(emb);
    k_gemm0<<<dim3(G4 / 128, NROW / 128), 256>>>(W_ih, b_ih, b_hh);
    k_fused<<<NGRID, 256, RNN_SMEM>>>(h0, c0, W_hh, W_out, b_out, out);
}